// round 15
// baseline (speedup 1.0000x reference)
#include <cuda_runtime.h>
#include <cuda_bf16.h>
#include <cstdint>

// Hamming1Layer v12: v10 math + cp.async prefetch of remote-bit planes.
// Remote bits 9..13 staged into SMEM one chunk ahead (register-free DMA);
// gather reads them at LDS latency. TPB=512, 1 block/SM, SMEM 224.5KB.
// B=32, C_IN=32, C_OUT=64, L=16384, N_BITS=14.

#define NBITS   14
#define LPOW    16384
#define CIN     32
#define COUT    64
#define TILE_L  512
#define CHUNK_L 128
#define NCHUNK  4
#define TPB     512

#define YROW    136
#define WROW    40
#define RBYTES  81920                  // 5 planes x 32 c x 128 l x 4B
#define SMEM_XB    0                   // bf16 [32][512] = 32768
#define SMEM_Y     32768               // [h/l][32][YROW] bf16 = 17408
#define SMEM_WH    50176               // 5120
#define SMEM_WL    55296               // 5120
#define SMEM_BIAS  60416               // 256
#define SMEM_RB    60672               // 2 x 81920 = 163840
#define SMEM_TOTAL 224512

__device__ __forceinline__ uint64_t pack2(float lo, float hi) {
    uint64_t r; asm("mov.b64 %0, {%1, %2};" : "=l"(r) : "f"(lo), "f"(hi)); return r;
}
__device__ __forceinline__ void unpack2(uint64_t v, float& lo, float& hi) {
    asm("mov.b64 {%0, %1}, %2;" : "=f"(lo), "=f"(hi) : "l"(v));
}
__device__ __forceinline__ uint64_t fma2(uint64_t a, uint64_t b, uint64_t c) {
    uint64_t d; asm("fma.rn.f32x2 %0, %1, %2, %3;" : "=l"(d) : "l"(a), "l"(b), "l"(c)); return d;
}
__device__ __forceinline__ uint64_t mul2(uint64_t a, uint64_t b) {
    uint64_t d; asm("mul.rn.f32x2 %0, %1, %2;" : "=l"(d) : "l"(a), "l"(b)); return d;
}
__device__ __forceinline__ uint64_t add2(uint64_t a, uint64_t b) {
    uint64_t d; asm("add.rn.f32x2 %0, %1, %2;" : "=l"(d) : "l"(a), "l"(b)); return d;
}
__device__ __forceinline__ uint64_t sub2(uint64_t a, uint64_t b) {
    uint64_t d; asm("sub.rn.f32x2 %0, %1, %2;" : "=l"(d) : "l"(a), "l"(b)); return d;
}
__device__ __forceinline__ uint64_t bfp_to_f32x2(uint32_t v) {
    uint32_t lo = v << 16, hi = v & 0xFFFF0000u;
    uint64_t r; asm("mov.b64 %0, {%1, %2};" : "=l"(r) : "r"(lo), "r"(hi)); return r;
}
__device__ __forceinline__ uint32_t f2_to_bfp(float a, float b) {
    uint32_t r; asm("cvt.rn.bf16x2.f32 %0, %1, %2;" : "=r"(r) : "f"(b), "f"(a)); return r;
}

#define CP_ASYNC16(dst, src) \
    asm volatile("cp.async.cg.shared.global [%0], [%1], 16;" :: "r"(dst), "l"(src))
#define CP_COMMIT()  asm volatile("cp.async.commit_group;" ::: "memory")
#define CP_WAIT(n)   asm volatile("cp.async.wait_group %0;" :: "n"(n) : "memory")

#define LDSM_X4_T(d, addr)                                                      \
    asm volatile("ldmatrix.sync.aligned.m8n8.x4.trans.shared.b16 "              \
                 "{%0,%1,%2,%3}, [%4];"                                         \
                 : "=r"((d)[0]), "=r"((d)[1]), "=r"((d)[2]), "=r"((d)[3])       \
                 : "r"(addr))
#define LDSM_X2(d0, d1, addr)                                                   \
    asm volatile("ldmatrix.sync.aligned.m8n8.x2.shared.b16 {%0,%1}, [%2];"      \
                 : "=r"(d0), "=r"(d1) : "r"(addr))
#define MMA_BF16(c, a, b0, b1)                                                  \
    asm volatile("mma.sync.aligned.m16n8k16.row.col.f32.bf16.bf16.f32 "         \
                 "{%0,%1,%2,%3}, {%4,%5,%6,%7}, {%8,%9}, {%0,%1,%2,%3};"        \
                 : "+f"((c)[0]), "+f"((c)[1]), "+f"((c)[2]), "+f"((c)[3])       \
                 : "r"((a)[0]), "r"((a)[1]), "r"((a)[2]), "r"((a)[3]),          \
                   "r"(b0), "r"(b1))

extern __shared__ unsigned char smem_raw[];

__global__ __launch_bounds__(TPB, 1)
void hamming_kernel(const float* __restrict__ x,
                    const float* __restrict__ w_self,
                    const float* __restrict__ w_bits,
                    const float* __restrict__ mix_w,
                    const float* __restrict__ mix_b,
                    float* __restrict__ out)
{
    uint32_t*      sh_xb   = (uint32_t*)(smem_raw + SMEM_XB);
    __nv_bfloat16* sh_wh   = (__nv_bfloat16*)(smem_raw + SMEM_WH);
    __nv_bfloat16* sh_wl   = (__nv_bfloat16*)(smem_raw + SMEM_WL);
    float*         sh_bias = (float*)(smem_raw + SMEM_BIAS);
    const uint32_t sbase   = (uint32_t)__cvta_generic_to_shared(smem_raw);

    const int tid   = threadIdx.x;
    const int wid   = tid >> 5;
    const int lane  = tid & 31;
    const int tile  = blockIdx.x;
    const int b     = blockIdx.y;
    const int lbase = tile * TILE_L;
    const float* xb = x + (size_t)b * CIN * LPOW;

    // ---- prefetch chunk 0 remote planes (bits 9..13) into rbuf[0] ----
    {
        #pragma unroll
        for (int j = 0; j < 10; ++j) {               // 5120 16B segs / 512 thr
            int idx = j * TPB + tid;
            int kp = idx >> 10, rem = idx & 1023, c = rem >> 5, q = rem & 31;
            const float* src = xb + (size_t)c * LPOW
                             + (lbase ^ (1 << (9 + kp))) + q * 4;
            CP_ASYNC16(sbase + SMEM_RB + idx * 16, src);
        }
        CP_COMMIT();
    }

    // ---- stage weights + bf16 x tile ----
    const float inv15 = 1.0f / 15.0f;
    for (int e = tid; e < CIN * COUT; e += TPB) {    // e = o*32 + c
        int o = e >> 5, c = e & 31;
        float w = mix_w[e] * inv15;
        __nv_bfloat16 wh = __float2bfloat16(w);
        sh_wh[o * WROW + c] = wh;
        sh_wl[o * WROW + c] = __float2bfloat16(w - __bfloat162float(wh));
    }
    if (tid < COUT) sh_bias[tid] = mix_b[tid];

    const float4* xg4 = (const float4*)xb;
    #pragma unroll
    for (int i = 0; i < (CIN * TILE_L / 4) / TPB; ++i) {   // 8 iters
        int j = i * TPB + tid, c = j >> 7, lw = j & 127;
        float4 f = xg4[(size_t)c * (LPOW / 4) + (lbase >> 2) + lw];
        uint2 p; p.x = f2_to_bfp(f.x, f.y); p.y = f2_to_bfp(f.z, f.w);
        *(uint2*)(sh_xb + c * (TILE_L / 2) + lw * 2) = p;
    }

    const float ws = *w_self;
    const uint64_t ws2 = pack2(ws, ws);
    uint64_t wb2[NBITS];
    #pragma unroll
    for (int k = 0; k < NBITS; ++k) { float v = w_bits[k]; wb2[k] = pack2(v, v); }

    // mix lane constants: 16 warps -> mt = wid>>1 (l tile), nh = wid&1 (o half)
    const int g = lane >> 2, t = lane & 3;
    const int mt = wid >> 1, nh = wid & 1;
    const int wbase = mt * 16;
    const int krow0 = (lane & 7) + ((lane >> 4) & 1) * 8;
    const int mcolA = ((lane >> 3) & 1) * 8;
    const int brow  = lane & 7;
    const int bk    = ((lane >> 3) & 1) * 8;
    const uint32_t whB = sbase + SMEM_WH;
    const uint32_t wlB = sbase + SMEM_WL;
    const uint32_t ybh = sbase + SMEM_Y;
    const uint32_t ybl = ybh + CIN * YROW * 2;
    unsigned char* ybh_w = smem_raw + SMEM_Y;
    unsigned char* ybl_w = ybh_w + CIN * YROW * 2;
    float* og = out + (size_t)b * COUT * LPOW;

    for (int ck = 0; ck < NCHUNK; ++ck) {
        // prefetch ck+1 remote planes; ensure ck's are complete
        if (ck < NCHUNK - 1) {
            int nb = (ck + 1) & 1;
            #pragma unroll
            for (int j = 0; j < 10; ++j) {
                int idx = j * TPB + tid;
                int kp = idx >> 10, rem = idx & 1023, c = rem >> 5, q = rem & 31;
                const float* src = xb + (size_t)c * LPOW
                                 + (lbase ^ (1 << (9 + kp))) + (ck + 1) * CHUNK_L + q * 4;
                CP_ASYNC16(sbase + SMEM_RB + nb * RBYTES + idx * 16, src);
            }
            CP_COMMIT();
            CP_WAIT(1);
        } else {
            CP_WAIT(0);
        }
        __syncthreads();    // rbuf[ck] visible; y free (mix ck-1 finished)

        // ========== gather: 2 items/thread, remote from SMEM ==========
        const float* rb = (const float*)(smem_raw + SMEM_RB + (ck & 1) * RBYTES);
        #pragma unroll
        for (int it = 0; it < 2; ++it) {
            int idx = it * TPB + tid;
            int c   = idx >> 5;              // 0..31
            int ql  = idx & 31;
            int qg  = ck * 32 + ql;

            const uint32_t* row = sh_xb + c * (TILE_L / 2);
            float4 s = ((const float4*)(xb + (size_t)c * LPOW))[(lbase >> 2) + qg];

            uint64_t s01 = pack2(s.x, s.y), s23 = pack2(s.z, s.w);
            uint64_t a01 = mul2(ws2, s01);
            uint64_t a23 = mul2(ws2, s23);
            a01 = fma2(wb2[0], pack2(s.y, s.x), a01);
            a23 = fma2(wb2[0], pack2(s.w, s.z), a23);
            a01 = fma2(wb2[1], s23, a01);
            a23 = fma2(wb2[1], s01, a23);

            uint64_t b01, b23;
            {
                uint2 n = *(const uint2*)(row + (qg ^ 1) * 2);
                b01 = mul2(wb2[2], bfp_to_f32x2(n.x));
                b23 = mul2(wb2[2], bfp_to_f32x2(n.y));
            }
            #pragma unroll
            for (int k = 3; k <= 8; ++k) {
                uint2 n = *(const uint2*)(row + (qg ^ (1 << (k - 2))) * 2);
                b01 = fma2(wb2[k], bfp_to_f32x2(n.x), b01);
                b23 = fma2(wb2[k], bfp_to_f32x2(n.y), b23);
            }
            #pragma unroll
            for (int kp = 0; kp < 5; ++kp) {
                float4 r = *(const float4*)(rb + (kp * 32 + c) * CHUNK_L + ql * 4);
                a01 = fma2(wb2[9 + kp], pack2(r.x, r.y), a01);
                a23 = fma2(wb2[9 + kp], pack2(r.z, r.w), a23);
            }
            a01 = add2(a01, b01);
            a23 = add2(a23, b23);

            float y0, y1, y2, y3;
            unpack2(a01, y0, y1);
            unpack2(a23, y2, y3);
            uint32_t hA = f2_to_bfp(y0, y1);
            uint32_t hB = f2_to_bfp(y2, y3);
            uint64_t r01 = sub2(a01, bfp_to_f32x2(hA));
            uint64_t r23 = sub2(a23, bfp_to_f32x2(hB));
            float r0, r1, r2, r3;
            unpack2(r01, r0, r1);
            unpack2(r23, r2, r3);
            int yoff = c * (YROW * 2) + ql * 8;
            *(uint2*)(ybh_w + yoff) = make_uint2(hA, hB);
            *(uint2*)(ybl_w + yoff) = make_uint2(f2_to_bfp(r0, r1), f2_to_bfp(r2, r3));
        }
        __syncthreads();    // y(ck) ready

        // ========== mix: warp (mt, nh) -> 16 l x 32 o ==========
        uint32_t Ah[2][4], Al[2][4];
        #pragma unroll
        for (int ks = 0; ks < 2; ++ks) {
            uint32_t off = (uint32_t)(((ks * 16 + krow0) * YROW + wbase + mcolA) * 2);
            LDSM_X4_T(Ah[ks], ybh + off);
            LDSM_X4_T(Al[ks], ybl + off);
        }

        float acc[4][4];
        #pragma unroll
        for (int nt = 0; nt < 4; ++nt) {
            float2 bb = *(float2*)(sh_bias + (nh * 4 + nt) * 8 + 2 * t);
            acc[nt][0] = bb.x; acc[nt][1] = bb.y;
            acc[nt][2] = bb.x; acc[nt][3] = bb.y;
        }

        #pragma unroll
        for (int ks = 0; ks < 2; ++ks) {
            #pragma unroll
            for (int nt = 0; nt < 4; ++nt) {
                uint32_t woff = (uint32_t)((((nh * 4 + nt) * 8 + brow) * WROW
                                + ks * 16 + bk) * 2);
                uint32_t bh0, bh1, bl0, bl1;
                LDSM_X2(bh0, bh1, whB + woff);
                MMA_BF16(acc[nt], Ah[ks], bh0, bh1);
                MMA_BF16(acc[nt], Al[ks], bh0, bh1);
                LDSM_X2(bl0, bl1, wlB + woff);
                MMA_BF16(acc[nt], Ah[ks], bl0, bl1);
            }
        }

        const int l0 = lbase + ck * CHUNK_L + wbase + g;
        #pragma unroll
        for (int nt = 0; nt < 4; ++nt) {
            int o0 = (nh * 4 + nt) * 8 + 2 * t;
            og[(size_t)o0 * LPOW + l0]           = acc[nt][0];
            og[(size_t)(o0 + 1) * LPOW + l0]     = acc[nt][1];
            og[(size_t)o0 * LPOW + l0 + 8]       = acc[nt][2];
            og[(size_t)(o0 + 1) * LPOW + l0 + 8] = acc[nt][3];
        }
    }
}

extern "C" void kernel_launch(void* const* d_in, const int* in_sizes, int n_in,
                              void* d_out, int out_size)
{
    const float* x      = (const float*)d_in[0];
    const float* w_self = (const float*)d_in[1];
    const float* w_bits = (const float*)d_in[2];
    const float* mix_w  = (const float*)d_in[3];
    const float* mix_b  = (const float*)d_in[4];
    float* out = (float*)d_out;

    cudaFuncSetAttribute(hamming_kernel,
                         cudaFuncAttributeMaxDynamicSharedMemorySize, SMEM_TOTAL);

    dim3 grid(LPOW / TILE_L, 32, 1);   // 1024 blocks, 512 thr
    hamming_kernel<<<grid, TPB, SMEM_TOTAL>>>(x, w_self, w_bits, mix_w, mix_b, out);
}